// round 17
// baseline (speedup 1.0000x reference)
#include <cuda_runtime.h>

// CenterLoss: mean_i ||x_i - centers[labels_i]||^2
//   = mean( ||x||^2 + ||c||^2 - 2 x.c )
// x: [4096, 512] f32, centers: [7001, 512] f32, labels: [4096] i32 -> out: [1] f32
//
// Record structure + Blackwell 256-bit loads (ld.global.nc.v8.f32):
// 4 LDG.256 per thread instead of 8 LDG.128 -> shortest issue stream yet.

#define BATCH 4096
#define DIM 512
#define NBLK 512
#define BLOCK 256
#define SPB 8             // samples per CTA; 4 groups of 64 threads, 2 samples each

__device__ float g_accum = 0.0f;       // single pre-scaled accumulator
__device__ unsigned int g_count = 0;

// 256-bit global load (sm_100+): one instruction fetches 8 floats.
#define LDG256(r, p)                                                        \
    asm volatile("ld.global.nc.v8.f32 {%0,%1,%2,%3,%4,%5,%6,%7}, [%8];"     \
        : "=f"((r)[0]), "=f"((r)[1]), "=f"((r)[2]), "=f"((r)[3]),           \
          "=f"((r)[4]), "=f"((r)[5]), "=f"((r)[6]), "=f"((r)[7])            \
        : "l"(p))

__global__ __launch_bounds__(BLOCK, 4)
void center_loss_kernel(const float* __restrict__ x,
                        const float* __restrict__ c,
                        const int2* __restrict__ labels2,
                        float* __restrict__ out)
{
    const int t = threadIdx.x;        // 0..255
    const int b = blockIdx.x;
    const int h = t >> 6;             // group 0..3 -> samples {2h, 2h+1}
    const int lane64 = t & 63;        // 8-float chunk within a row
    const int base = b * SPB + h * 2;
    const int coff = lane64 * 8;      // element offset within a row

    // One int2 per group: both labels in one load.
    const int2 lv = __ldg(&labels2[b * 4 + h]);
    const int labs[2] = { lv.x, lv.y };

    // Decomposed accumulation; 4 x LDG.256 per thread, each consumed
    // immediately and independently.
    float axx = 0.0f, acc_ = 0.0f, axc = 0.0f;
#pragma unroll
    for (int s = 0; s < 2; s++) {
        float xv[8], cv[8];
        LDG256(xv, x + (size_t)(base + s) * DIM + coff);
        LDG256(cv, c + (size_t)labs[s] * DIM + coff);
#pragma unroll
        for (int i = 0; i < 8; i++) axx = fmaf(xv[i], xv[i], axx);
#pragma unroll
        for (int i = 0; i < 8; i++) acc_ = fmaf(cv[i], cv[i], acc_);
#pragma unroll
        for (int i = 0; i < 8; i++) axc = fmaf(xv[i], cv[i], axc);
    }
    float acc = axx + acc_ - 2.0f * axc;

    // Warp reduce
#pragma unroll
    for (int o = 16; o; o >>= 1) acc += __shfl_xor_sync(0xffffffffu, acc, o);

    __shared__ float ws[BLOCK / 32];
    if ((t & 31) == 0) ws[t >> 5] = acc;
    __syncthreads();

    // Thread 0 only: one pre-scaled RED + acq_rel ticket; last CTA reads 1 float.
    if (t == 0) {
        float p = 0.0f;
#pragma unroll
        for (int w = 0; w < BLOCK / 32; w++) p += ws[w];
        // Posted reduction (no return), pre-scaled so accumulator == mean.
        asm volatile("red.add.relaxed.gpu.global.f32 [%0], %1;"
                     :: "l"(&g_accum), "f"(p * (1.0f / (float)BATCH))
                     : "memory");
        // Release orders the RED above; acquire covers the read below.
        unsigned int v;
        asm volatile("atom.add.acq_rel.gpu.global.u32 %0, [%1], 1;"
                     : "=r"(v) : "l"(&g_count) : "memory");
        const bool last = (v == NBLK - 1);
        float s = 0.0f;
        if (last) {
            asm volatile("ld.global.cg.f32 %0, [%1];"
                         : "=f"(s) : "l"(&g_accum) : "memory");
            out[0] = s;
            asm volatile("st.global.cg.f32 [%0], 0f00000000;"
                         :: "l"(&g_accum) : "memory");   // reset accumulator
            asm volatile("st.global.cg.u32 [%0], 0;"
                         :: "l"(&g_count) : "memory");   // reset ticket
        }
    }
}

extern "C" void kernel_launch(void* const* d_in, const int* in_sizes, int n_in,
                              void* d_out, int out_size)
{
    const float* x = (const float*)d_in[0];
    const float* c = (const float*)d_in[1];
    const int2* labels2 = (const int2*)d_in[2];
    float* out = (float*)d_out;
    center_loss_kernel<<<NBLK, BLOCK>>>(x, c, labels2, out);
}